// round 2
// baseline (speedup 1.0000x reference)
#include <cuda_runtime.h>
#include <cuda_fp16.h>

// Problem constants (fixed by the reference)
#define Bb    4
#define Tt    16
#define Hh    64
#define Ww    64
#define Cc    256
#define NCLS  512
#define TAPS  27

#define WCHUNK 32      // w positions per block
#define RS     260     // stage row stride in floats (256 + 4 pad, keeps 16B align)

// Transposed, fp16, pre-scaled (x0.5) weight table: [class][tap][channel]
__device__ __align__(16) __half g_wt[NCLS * TAPS * Cc];

// ---------------------------------------------------------------------------
// Kernel A: transpose + convert weights.
// weight layout: [C][NC][kT][kH][kW] row-major -> w[(c*NC+n)*27 + k]
// ---------------------------------------------------------------------------
__global__ void wt_transpose_kernel(const float* __restrict__ w)
{
    int tid = blockIdx.x * blockDim.x + threadIdx.x;
    const int total = Cc * NCLS * TAPS;
    if (tid >= total) return;
    int k = tid % TAPS;
    int n = (tid / TAPS) % NCLS;
    int c = tid / (TAPS * NCLS);
    // Pre-scale by 0.5; main kernel uses fmaf(v, 2.0f, acc) -> FFMA-imm (rt=1)
    g_wt[(n * TAPS + k) * Cc + c] = __float2half_rn(0.5f * w[tid]);
}

// ---------------------------------------------------------------------------
// Kernel B: main gather-accumulate.
// Block = 256 threads = 8 warps, handles one (b, t, h, w-chunk of 32).
//   warp (2 per position): ch-half = (warp&1)*128, position-in-pass = warp>>1
//   lane holds 4 channels (float4 acc) -> conflict-free STS.128 into stage
// 8 passes x 4 positions = 32 w. Then coalesced write-out from SMEM stage.
// ---------------------------------------------------------------------------
__global__ void __launch_bounds__(256) onehot_conv_kernel(
    const int*   __restrict__ indices,
    const float* __restrict__ bias,
    float*       __restrict__ out)
{
    // NOTE: explicit 16B alignment — R1 failed with "misaligned address"
    // because s_stage landed at smem offset 1224 (8 mod 16) and float4
    // smem accesses require 16B alignment.
    __shared__ __align__(16) float s_stage[WCHUNK * RS];   // [w][c] padded
    __shared__ __align__(16) int   s_idx[9 * 34];          // (dt,dh) x (w halo)

    const int bx   = blockIdx.x;
    const int wblk = bx & 1;                 // W / WCHUNK = 2
    const int h    = (bx >> 1) & 63;
    const int t    = (bx >> 7) & 15;
    const int b    = bx >> 11;
    const int w0   = wblk * WCHUNK;

    const int tid = threadIdx.x;

    // Load index halo: 9 (dt,dh) rows x 34 w-columns, with edge clamping.
    // Temporal pad: causal edge (front 2). Spatial pads: edge 1 each side.
    for (int i = tid; i < 9 * 34; i += 256) {
        int r  = i / 34, j = i % 34;
        int dt = r / 3,  dh = r % 3;
        int st = t + dt - 2; if (st < 0) st = 0;
        int sh = h + dh - 1; if (sh < 0) sh = 0; if (sh > Hh - 1) sh = Hh - 1;
        int gw = w0 + j - 1; if (gw < 0) gw = 0; if (gw > Ww - 1) gw = Ww - 1;
        s_idx[i] = indices[((b * Tt + st) * Hh + sh) * Ww + gw];
    }
    __syncthreads();

    const int warp  = tid >> 5;
    const int lane  = tid & 31;
    const int ch0   = (warp & 1) << 7;    // 0 or 128
    const int posw  = warp >> 1;          // 0..3
    const int cbase = ch0 + 4 * lane;     // this lane's 4 channels

    const float4 bz = *reinterpret_cast<const float4*>(bias + cbase);

    #pragma unroll 1
    for (int p = 0; p < 8; p++) {
        const int w_l = p * 4 + posw;     // 0..31
        float4 a = bz;

        #pragma unroll
        for (int r = 0; r < 9; r++) {
            #pragma unroll
            for (int dw = 0; dw < 3; dw++) {
                const int k   = r * 3 + dw;
                const int cls = s_idx[r * 34 + w_l + dw];
                const __half* rowp = g_wt + (cls * TAPS + k) * Cc + cbase;
                uint2 u = *reinterpret_cast<const uint2*>(rowp);   // LDG.64, coalesced across warp
                __half2 v0 = *reinterpret_cast<__half2*>(&u.x);
                __half2 v1 = *reinterpret_cast<__half2*>(&u.y);
                float2 f0 = __half22float2(v0);
                float2 f1 = __half22float2(v1);
                a.x = fmaf(f0.x, 2.0f, a.x);
                a.y = fmaf(f0.y, 2.0f, a.y);
                a.z = fmaf(f1.x, 2.0f, a.z);
                a.w = fmaf(f1.y, 2.0f, a.w);
            }
        }
        // conflict-free: 32 lanes store 512B contiguous within row w_l
        *reinterpret_cast<float4*>(&s_stage[w_l * RS + cbase]) = a;
    }
    __syncthreads();

    // Write-out: warp takes channel-quads; lane = w. STG is 128B coalesced per channel.
    const size_t THW   = (size_t)Tt * Hh * Ww;
    const size_t obase = (size_t)b * Cc * THW + (size_t)t * (Hh * Ww) + (size_t)h * Ww + w0;
    for (int c4 = warp; c4 < Cc / 4; c4 += 8) {
        float4 v = *reinterpret_cast<const float4*>(&s_stage[lane * RS + 4 * c4]);
        const int c = 4 * c4;
        out[obase + (size_t)(c + 0) * THW + lane] = v.x;
        out[obase + (size_t)(c + 1) * THW + lane] = v.y;
        out[obase + (size_t)(c + 2) * THW + lane] = v.z;
        out[obase + (size_t)(c + 3) * THW + lane] = v.w;
    }
}

// ---------------------------------------------------------------------------
extern "C" void kernel_launch(void* const* d_in, const int* in_sizes, int n_in,
                              void* d_out, int out_size)
{
    const int*   indices = (const int*)  d_in[0];
    const float* weight  = (const float*)d_in[1];
    const float* bias    = (const float*)d_in[2];
    float*       out     = (float*)d_out;

    const int total = Cc * NCLS * TAPS;
    wt_transpose_kernel<<<(total + 255) / 256, 256>>>(weight);

    const int grid = Bb * Tt * Hh * (Ww / WCHUNK);   // 8192
    onehot_conv_kernel<<<grid, 256>>>(indices, bias, out);
}

// round 3
// speedup vs baseline: 1.2382x; 1.2382x over previous
#include <cuda_runtime.h>
#include <cuda_fp16.h>

// Problem constants
#define Bb    4
#define Tt    16
#define Hh    64
#define Ww    64
#define Cc    256
#define NCLS  512
#define TAPS  27
#define WCHUNK 32
#define WOFF_BYTES (TAPS * Cc * 2)   // 13824 bytes per class row-block

// Transposed fp16 weight table: [class][tap][channel]
__device__ __align__(16) __half g_wt[NCLS * TAPS * Cc];

// ---------------------------------------------------------------------------
// Kernel A: transpose + fp16 convert, smem-tiled so both sides are coalesced.
// weight[c][n][k] row-major. Block handles (class n, 32-channel tile).
// ---------------------------------------------------------------------------
__global__ void __launch_bounds__(256) wt_transpose_kernel(const float* __restrict__ w)
{
    __shared__ float s[32 * 27];     // [c_local][k], stride 27 (odd) -> conflict-free
    const int bx  = blockIdx.x;
    const int n   = bx >> 3;         // class
    const int c0  = (bx & 7) * 32;   // channel tile
    const int tid = threadIdx.x;

    for (int i = tid; i < 32 * 27; i += 256) {
        int cl = i / 27, k = i % 27;
        s[i] = w[(size_t)(c0 + cl) * (NCLS * TAPS) + n * TAPS + k];  // 108B runs, coalesced
    }
    __syncthreads();
    for (int j = tid; j < 32 * 27; j += 256) {
        int k = j >> 5, cl = j & 31;
        g_wt[(n * TAPS + k) * Cc + c0 + cl] = __float2half_rn(s[cl * 27 + k]);  // 64B coalesced
    }
}

// ---------------------------------------------------------------------------
// Kernel B: gather-accumulate.
// Block = 256 thr = 8 warps, one (b,t,h, 32-w chunk). Warp owns ONE position
// per pass (4 passes x 8 warps = 32 w). Lane owns channels {4l..4l+3} and
// {128+4l..128+4l+3}. Taps paired in fp16 (HADD2) before fp32 accumulate.
// Class byte-offsets preloaded to one register/lane, shuffled in the loop.
// Output staged via XOR-swizzled smem (conflict-free both directions).
// ---------------------------------------------------------------------------
__global__ void __launch_bounds__(256) onehot_conv_kernel(
    const int*   __restrict__ indices,
    const float* __restrict__ bias,
    float*       __restrict__ out)
{
    __shared__ __align__(16) float4 s_stage[WCHUNK * 64];   // [w][quad], swizzled, 32KB
    __shared__ int s_off[9 * 34];                           // class byte-offsets, halo'd in w

    const int bx   = blockIdx.x;
    const int wblk = bx & 1;
    const int h    = (bx >> 1) & 63;
    const int t    = (bx >> 7) & 15;
    const int b    = bx >> 11;
    const int w0   = wblk * WCHUNK;
    const int tid  = threadIdx.x;

    // Halo of class offsets: 9 (dt,dh) rows x 34 w, edge-clamped.
    for (int i = tid; i < 9 * 34; i += 256) {
        int r  = i / 34, j = i % 34;
        int dt = r / 3,  dh = r % 3;
        int st = t + dt - 2; if (st < 0) st = 0;
        int sh = h + dh - 1; if (sh < 0) sh = 0; if (sh > Hh - 1) sh = Hh - 1;
        int gw = w0 + j - 1; if (gw < 0) gw = 0; if (gw > Ww - 1) gw = Ww - 1;
        s_off[i] = indices[((b * Tt + st) * Hh + sh) * Ww + gw] * WOFF_BYTES;
    }
    __syncthreads();

    const int warp = tid >> 5;
    const int lane = tid & 31;
    const int kl   = lane < 27 ? lane : 26;     // lane -> tap (guarded)
    const int rIdx = (kl / 3) * 34 + (kl % 3);  // row part of s_off index

    const char* wtb   = reinterpret_cast<const char*>(g_wt);
    const char* base0 = wtb + lane * 8;               // channels 4l..4l+3 (fp16 x4 = 8B)
    const char* base1 = wtb + 256 + lane * 8;         // channels 128+4l..

    const float4 bz0 = *reinterpret_cast<const float4*>(bias + 4 * lane);
    const float4 bz1 = *reinterpret_cast<const float4*>(bias + 128 + 4 * lane);

    #pragma unroll 1
    for (int p = 0; p < 4; p++) {
        const int w_l = p * 8 + warp;
        // each lane holds the class byte-offset for tap `lane` at this position
        const int myoff = s_off[rIdx + w_l];

        float4 a0 = bz0, a1 = bz1;

        #pragma unroll
        for (int k = 0; k < 26; k += 2) {
            const int o0 = __shfl_sync(0xffffffffu, myoff, k);
            const int o1 = __shfl_sync(0xffffffffu, myoff, k + 1);
            uint2 u0a = *reinterpret_cast<const uint2*>(base0 + o0 + k * 512);
            uint2 u0b = *reinterpret_cast<const uint2*>(base1 + o0 + k * 512);
            uint2 u1a = *reinterpret_cast<const uint2*>(base0 + o1 + (k + 1) * 512);
            uint2 u1b = *reinterpret_cast<const uint2*>(base1 + o1 + (k + 1) * 512);
            __half2 s0 = __hadd2(*reinterpret_cast<__half2*>(&u0a.x), *reinterpret_cast<__half2*>(&u1a.x));
            __half2 s1 = __hadd2(*reinterpret_cast<__half2*>(&u0a.y), *reinterpret_cast<__half2*>(&u1a.y));
            __half2 s2 = __hadd2(*reinterpret_cast<__half2*>(&u0b.x), *reinterpret_cast<__half2*>(&u1b.x));
            __half2 s3 = __hadd2(*reinterpret_cast<__half2*>(&u0b.y), *reinterpret_cast<__half2*>(&u1b.y));
            float2 f;
            f = __half22float2(s0); a0.x += f.x; a0.y += f.y;
            f = __half22float2(s1); a0.z += f.x; a0.w += f.y;
            f = __half22float2(s2); a1.x += f.x; a1.y += f.y;
            f = __half22float2(s3); a1.z += f.x; a1.w += f.y;
        }
        {   // tap 26 (unpaired)
            const int o = __shfl_sync(0xffffffffu, myoff, 26);
            uint2 ua = *reinterpret_cast<const uint2*>(base0 + o + 26 * 512);
            uint2 ub = *reinterpret_cast<const uint2*>(base1 + o + 26 * 512);
            float2 f;
            f = __half22float2(*reinterpret_cast<__half2*>(&ua.x)); a0.x += f.x; a0.y += f.y;
            f = __half22float2(*reinterpret_cast<__half2*>(&ua.y)); a0.z += f.x; a0.w += f.y;
            f = __half22float2(*reinterpret_cast<__half2*>(&ub.x)); a1.x += f.x; a1.y += f.y;
            f = __half22float2(*reinterpret_cast<__half2*>(&ub.y)); a1.z += f.x; a1.w += f.y;
        }

        // XOR-swizzled store: logical quad q at phys q^(w&31); conflict-free.
        const int sw = w_l & 31;
        s_stage[w_l * 64 + (lane ^ sw)]        = a0;
        s_stage[w_l * 64 + 32 + (lane ^ sw)]   = a1;
    }
    __syncthreads();

    // Read-back: warp takes logical quads qq = warp, warp+8, ...; lane = w.
    // phys = qq ^ (lane&31) keeps bit5 -> conflict-free LDS.128.
    const size_t THW   = (size_t)Tt * Hh * Ww;
    const size_t obase = (size_t)b * Cc * THW + (size_t)t * (Hh * Ww) + (size_t)h * Ww + w0;
    #pragma unroll
    for (int qq = warp; qq < 64; qq += 8) {
        float4 v = s_stage[lane * 64 + (qq ^ (lane & 31))];
        const int c = qq * 4;
        out[obase + (size_t)(c + 0) * THW + lane] = v.x;
        out[obase + (size_t)(c + 1) * THW + lane] = v.y;
        out[obase + (size_t)(c + 2) * THW + lane] = v.z;
        out[obase + (size_t)(c + 3) * THW + lane] = v.w;
    }
}

// ---------------------------------------------------------------------------
extern "C" void kernel_launch(void* const* d_in, const int* in_sizes, int n_in,
                              void* d_out, int out_size)
{
    const int*   indices = (const int*)  d_in[0];
    const float* weight  = (const float*)d_in[1];
    const float* bias    = (const float*)d_in[2];
    float*       out     = (float*)d_out;

    wt_transpose_kernel<<<NCLS * (Cc / 32), 256>>>(weight);

    const int grid = Bb * Tt * Hh * (Ww / WCHUNK);   // 8192
    onehot_conv_kernel<<<grid, 256>>>(indices, bias, out);
}